// round 16
// baseline (speedup 1.0000x reference)
#include <cuda_runtime.h>
#include <cuda_fp16.h>
#include <cstdint>

// ---------------------------------------------------------------------------
// Attention_37074157699274 — round 16: ONE persistent mega-kernel.
// 296 CTAs pull tickets from a global queue: [12288 K1 tiles][4096 attn
// groups][2048 K3 tiles]. Per-rowblock done-counters gate attn (needs 12 K1
// tiles) and K3 (needs 4 attn groups). Task bodies = round-11 proven code.
// Overlaps attn's DRAM time under GEMM tensor time in one stream.
//   K0: x->fp16 ; T1/T2: weights -> [N,K] fp16 ; R: reset counters
// ---------------------------------------------------------------------------

#define TOKENS   131072
#define GROUPS   4096
#define DIMX     256
#define NQKV     1536
#define INNER    512
#define HEADS    8
#define DH       64
#define ATT_SCALE 0.125f

#define K1_TILES 12288              // (1536/128) * (131072/128)
#define AT_END   (K1_TILES + GROUPS)        // 16384
#define TOTALT   (AT_END + 2048)            // + (256/128)*(131072/128)
#define NPCTA    296

__device__ __half g_xh  [(size_t)TOKENS * DIMX];
__device__ __half g_qkv [(size_t)TOKENS * NQKV];
__device__ __half g_attn[(size_t)TOKENS * INNER];
__device__ __half g_WqkvT[(size_t)NQKV * DIMX];
__device__ __half g_WoutT[(size_t)DIMX * INNER];

__device__ unsigned g_ticket;
__device__ int g_cnt1[1024];        // K1 tiles done per 128-row block (->12)
__device__ int g_cnt2[1024];        // attn groups done per 128-row block (->4)

// ------------------------- helpers ------------------------------------------

__device__ __forceinline__ uint32_t pack2h(float x, float y) {
    __half2 h = __halves2half2(__float2half_rn(x), __float2half_rn(y));
    return *reinterpret_cast<uint32_t*>(&h);
}
__device__ __forceinline__ uint32_t smem_u32(const void* p) {
    uint32_t a;
    asm("{ .reg .u64 t; cvta.to.shared.u64 t, %1; cvt.u32.u64 %0, t; }"
        : "=r"(a) : "l"(p));
    return a;
}
__device__ __forceinline__ void cp16(uint32_t saddr, const void* gptr) {
    asm volatile("cp.async.cg.shared.global [%0], [%1], 16;"
                 :: "r"(saddr), "l"(gptr) : "memory");
}
__device__ __forceinline__ void ldsm4(uint32_t r[4], uint32_t addr) {
    asm volatile("ldmatrix.sync.aligned.m8n8.x4.shared.b16 {%0,%1,%2,%3}, [%4];"
                 : "=r"(r[0]), "=r"(r[1]), "=r"(r[2]), "=r"(r[3]) : "r"(addr));
}
__device__ __forceinline__ void ldsm4t(uint32_t r[4], uint32_t addr) {
    asm volatile("ldmatrix.sync.aligned.m8n8.x4.trans.shared.b16 {%0,%1,%2,%3}, [%4];"
                 : "=r"(r[0]), "=r"(r[1]), "=r"(r[2]), "=r"(r[3]) : "r"(addr));
}
__device__ __forceinline__ void mma_f16(float c[4], uint32_t a0, uint32_t a1,
                                        uint32_t a2, uint32_t a3,
                                        uint32_t b0, uint32_t b1) {
    asm volatile(
        "mma.sync.aligned.m16n8k16.row.col.f32.f16.f16.f32 "
        "{%0,%1,%2,%3}, {%4,%5,%6,%7}, {%8,%9}, {%0,%1,%2,%3};\n"
        : "+f"(c[0]), "+f"(c[1]), "+f"(c[2]), "+f"(c[3])
        : "r"(a0), "r"(a1), "r"(a2), "r"(a3), "r"(b0), "r"(b1));
}
__device__ __forceinline__ int ld_cg(const int* p) {
    int v;
    asm volatile("ld.global.cg.b32 %0, [%1];" : "=r"(v) : "l"(p));
    return v;
}

// ------------------------- GEMM tile (round-11 body) ------------------------
// C[M,N] tile (128x128) at (bx,by) of A[M,K] @ Bt[N,K]^T (+bias).
// K-chunk 64, 3-stage cp.async ring, 8 warps 2(M)x4(N), warp tile 64x32.

#define STRB   144
#define A_BYTES (128 * STRB)
#define B_BYTES (128 * STRB)
#define STG_BYTES (A_BYTES + B_BYTES)
#define NSTG   3
#define GSM_BYTES (NSTG * STG_BYTES)      // 110592

__device__ __forceinline__ void gemm_tile(
    const __half* __restrict__ A, const __half* __restrict__ Bt,
    void* __restrict__ C, int K, int N, const float* __restrict__ bias,
    bool halfOut, int bx, int by, __half* sh)
{
    const uint32_t sb = smem_u32(sh);
    const int t     = threadIdx.x;
    const int lane  = t & 31;
    const int warp  = t >> 5;
    const int warpM = warp & 1;
    const int warpN = warp >> 1;

    const size_t rowBase = (size_t)by * 128;
    const int    colBase = bx * 128;
    const int NC = K >> 6;

    float acc[4][4][4];
    #pragma unroll
    for (int mt = 0; mt < 4; mt++)
        #pragma unroll
        for (int nt = 0; nt < 4; nt++)
            #pragma unroll
            for (int i = 0; i < 4; i++) acc[mt][nt][i] = 0.f;

    const __half* Ab = A  + rowBase * K;
    const __half* Bb = Bt + (size_t)colBase * K;

    auto stage = [&](int kc) {
        const int slot = kc % NSTG;
        const uint32_t aD = sb + slot * STG_BYTES;
        const uint32_t bD = aD + A_BYTES;
        const __half* As = Ab + kc * 64;
        const __half* Bs = Bb + kc * 64;
        #pragma unroll
        for (int i = 0; i < 4; i++) {
            int g = i * 256 + t, r = g >> 3, s = g & 7;
            cp16(aD + r * STRB + s * 16, As + (size_t)r * K + s * 8);
        }
        #pragma unroll
        for (int i = 0; i < 4; i++) {
            int g = i * 256 + t, r = g >> 3, s = g & 7;
            cp16(bD + r * STRB + s * 16, Bs + (size_t)r * K + s * 8);
        }
        asm volatile("cp.async.commit_group;" ::: "memory");
    };

    stage(0); stage(1);

    const int lr    = lane & 15;
    const int aKoff = (lane & 16) ? 16 : 0;
    const int bRow  = (lane & 7) + ((lane & 16) ? 8 : 0);
    const int bKoff = (lane & 8) ? 16 : 0;

    for (int kc = 0; kc < NC; kc++) {
        if (kc < NC - 1) asm volatile("cp.async.wait_group 1;" ::: "memory");
        else             asm volatile("cp.async.wait_group 0;" ::: "memory");
        __syncthreads();
        if (kc + 2 < NC) stage(kc + 2);

        const uint32_t aB = sb + (kc % NSTG) * STG_BYTES;
        const uint32_t bB = aB + A_BYTES;

        #pragma unroll
        for (int ks = 0; ks < 4; ks++) {
            const int k0b = ks * 32;
            uint32_t a[4][4], b[2][4];
            #pragma unroll
            for (int mt = 0; mt < 4; mt++)
                ldsm4(a[mt], aB + (warpM * 64 + mt * 16 + lr) * STRB + k0b + aKoff);
            #pragma unroll
            for (int np = 0; np < 2; np++)
                ldsm4(b[np], bB + (warpN * 32 + np * 16 + bRow) * STRB + k0b + bKoff);
            #pragma unroll
            for (int nt = 0; nt < 4; nt++) {
                uint32_t b0 = b[nt >> 1][(nt & 1) * 2];
                uint32_t b1 = b[nt >> 1][(nt & 1) * 2 + 1];
                #pragma unroll
                for (int mt = 0; mt < 4; mt++)
                    mma_f16(acc[mt][nt], a[mt][0], a[mt][1], a[mt][2], a[mt][3],
                            b0, b1);
            }
        }
    }

    #pragma unroll
    for (int mt = 0; mt < 4; mt++) {
        size_t row = rowBase + warpM * 64 + mt * 16 + (lane >> 2);
        #pragma unroll
        for (int nt = 0; nt < 4; nt++) {
            int col = colBase + warpN * 32 + nt * 8 + 2 * (lane & 3);
            if (halfOut) {
                __half* cp = (__half*)C;
                *(uint32_t*)(cp + row * N + col) =
                    pack2h(acc[mt][nt][0], acc[mt][nt][1]);
                *(uint32_t*)(cp + (row + 8) * N + col) =
                    pack2h(acc[mt][nt][2], acc[mt][nt][3]);
            } else {
                float b0 = bias[col], b1 = bias[col + 1];
                float* cp = (float*)C;
                *(float2*)(cp + row * N + col) =
                    make_float2(acc[mt][nt][0] + b0, acc[mt][nt][1] + b1);
                *(float2*)(cp + (row + 8) * N + col) =
                    make_float2(acc[mt][nt][2] + b0, acc[mt][nt][3] + b1);
            }
        }
    }
}

// ------------------------- attn group (round-11 body) -----------------------

#define ROWH 1544
#define ROWB (ROWH * 2)
#define ASM_BYTES (32 * ROWB)             // 98816 < GSM_BYTES

__device__ __forceinline__ void attn_group(
    const __half* __restrict__ qkv, __half* __restrict__ o, int grp, __half* T)
{
    const uint32_t tb = smem_u32(T);
    const int t    = threadIdx.x;
    const int lane = t & 31;
    const int h    = t >> 5;
    const size_t tokBase = (size_t)grp * 32;

    {
        const __half* src = qkv + tokBase * NQKV;
        #pragma unroll
        for (int i = 0; i < 24; i++) {
            int idx = i * 256 + t;
            int r = idx / 192, c = idx % 192;
            *(uint4*)(T + r * ROWH + c * 8) =
                *(const uint4*)(src + (size_t)r * NQKV + c * 8);
        }
    }
    __syncthreads();

    const uint32_t qOff = tb + h * 128;
    const uint32_t kOff = tb + 1024 + h * 128;
    const uint32_t vOff = tb + 2048 + h * 128;

    const int lr    = lane & 15;
    const int aKoff = (lane & 16) ? 16 : 0;
    const int bRow  = (lane & 7) + ((lane & 16) ? 8 : 0);
    const int bKoff = (lane & 8) ? 16 : 0;
    const int vCoff = (lane & 16) ? 16 : 0;

    float s[2][4][4];
    #pragma unroll
    for (int mt = 0; mt < 2; mt++)
        #pragma unroll
        for (int nt = 0; nt < 4; nt++)
            #pragma unroll
            for (int i = 0; i < 4; i++) s[mt][nt][i] = 0.f;

    #pragma unroll
    for (int kt = 0; kt < 4; kt++) {
        const int k0b = kt * 32;
        uint32_t a[2][4], b[2][4];
        #pragma unroll
        for (int mt = 0; mt < 2; mt++)
            ldsm4(a[mt], qOff + (mt * 16 + lr) * ROWB + k0b + aKoff);
        #pragma unroll
        for (int nb = 0; nb < 2; nb++)
            ldsm4(b[nb], kOff + (nb * 16 + bRow) * ROWB + k0b + bKoff);
        #pragma unroll
        for (int mt = 0; mt < 2; mt++)
            #pragma unroll
            for (int nb = 0; nb < 2; nb++) {
                mma_f16(s[mt][2 * nb    ], a[mt][0], a[mt][1], a[mt][2], a[mt][3],
                        b[nb][0], b[nb][1]);
                mma_f16(s[mt][2 * nb + 1], a[mt][0], a[mt][1], a[mt][2], a[mt][3],
                        b[nb][2], b[nb][3]);
            }
    }

    #pragma unroll
    for (int mt = 0; mt < 2; mt++)
        #pragma unroll
        for (int nt = 0; nt < 4; nt++)
            #pragma unroll
            for (int i = 0; i < 4; i++) s[mt][nt][i] *= ATT_SCALE;

    #pragma unroll
    for (int mt = 0; mt < 2; mt++) {
        float mA = -1e30f, mB = -1e30f;
        #pragma unroll
        for (int nt = 0; nt < 4; nt++) {
            mA = fmaxf(mA, fmaxf(s[mt][nt][0], s[mt][nt][1]));
            mB = fmaxf(mB, fmaxf(s[mt][nt][2], s[mt][nt][3]));
        }
        mA = fmaxf(mA, __shfl_xor_sync(~0u, mA, 1));
        mA = fmaxf(mA, __shfl_xor_sync(~0u, mA, 2));
        mB = fmaxf(mB, __shfl_xor_sync(~0u, mB, 1));
        mB = fmaxf(mB, __shfl_xor_sync(~0u, mB, 2));
        float sA = 0.f, sB = 0.f;
        #pragma unroll
        for (int nt = 0; nt < 4; nt++) {
            s[mt][nt][0] = __expf(s[mt][nt][0] - mA); sA += s[mt][nt][0];
            s[mt][nt][1] = __expf(s[mt][nt][1] - mA); sA += s[mt][nt][1];
            s[mt][nt][2] = __expf(s[mt][nt][2] - mB); sB += s[mt][nt][2];
            s[mt][nt][3] = __expf(s[mt][nt][3] - mB); sB += s[mt][nt][3];
        }
        sA += __shfl_xor_sync(~0u, sA, 1);
        sA += __shfl_xor_sync(~0u, sA, 2);
        sB += __shfl_xor_sync(~0u, sB, 1);
        sB += __shfl_xor_sync(~0u, sB, 2);
        float iA = 1.f / sA, iB = 1.f / sB;
        #pragma unroll
        for (int nt = 0; nt < 4; nt++) {
            s[mt][nt][0] *= iA; s[mt][nt][1] *= iA;
            s[mt][nt][2] *= iB; s[mt][nt][3] *= iB;
        }
    }

    uint32_t pk[2][2][4];
    #pragma unroll
    for (int mt = 0; mt < 2; mt++)
        #pragma unroll
        for (int kt = 0; kt < 2; kt++) {
            pk[mt][kt][0] = pack2h(s[mt][2 * kt    ][0], s[mt][2 * kt    ][1]);
            pk[mt][kt][1] = pack2h(s[mt][2 * kt    ][2], s[mt][2 * kt    ][3]);
            pk[mt][kt][2] = pack2h(s[mt][2 * kt + 1][0], s[mt][2 * kt + 1][1]);
            pk[mt][kt][3] = pack2h(s[mt][2 * kt + 1][2], s[mt][2 * kt + 1][3]);
        }

    float oa[2][8][4];
    #pragma unroll
    for (int mt = 0; mt < 2; mt++)
        #pragma unroll
        for (int nt = 0; nt < 8; nt++)
            #pragma unroll
            for (int i = 0; i < 4; i++) oa[mt][nt][i] = 0.f;

    #pragma unroll
    for (int kt = 0; kt < 2; kt++) {
        #pragma unroll
        for (int hf = 0; hf < 4; hf++) {
            uint32_t b[4];
            ldsm4t(b, vOff + (kt * 16 + lr) * ROWB + hf * 32 + vCoff);
            #pragma unroll
            for (int mt = 0; mt < 2; mt++) {
                mma_f16(oa[mt][2 * hf    ], pk[mt][kt][0], pk[mt][kt][1],
                        pk[mt][kt][2], pk[mt][kt][3], b[0], b[1]);
                mma_f16(oa[mt][2 * hf + 1], pk[mt][kt][0], pk[mt][kt][1],
                        pk[mt][kt][2], pk[mt][kt][3], b[2], b[3]);
            }
        }
    }

    __half* obase = o + tokBase * INNER + h * DH;
    #pragma unroll
    for (int mt = 0; mt < 2; mt++) {
        int row = mt * 16 + (lane >> 2);
        #pragma unroll
        for (int nt = 0; nt < 8; nt++) {
            int col = nt * 8 + 2 * (lane & 3);
            *(uint32_t*)(obase + (size_t)row * INNER + col) =
                pack2h(oa[mt][nt][0], oa[mt][nt][1]);
            *(uint32_t*)(obase + (size_t)(row + 8) * INNER + col) =
                pack2h(oa[mt][nt][2], oa[mt][nt][3]);
        }
    }
}

// ------------------------- mega kernel --------------------------------------

__global__ __launch_bounds__(256)
void mega(const __half* __restrict__ xh, const __half* __restrict__ wqT,
          const __half* __restrict__ woT, const float* __restrict__ bias,
          __half* __restrict__ qkv, __half* __restrict__ att,
          float* __restrict__ out)
{
    extern __shared__ __half sh[];
    __shared__ unsigned sid;
    const int t = threadIdx.x;

    for (;;) {
        if (t == 0) sid = atomicAdd(&g_ticket, 1u);
        __syncthreads();
        const unsigned id = sid;
        if (id >= TOTALT) return;

        if (id < K1_TILES) {
            // K1 tile: bx = id % 12, by = id / 12
            const int bx = (int)(id % 12u);
            const int by = (int)(id / 12u);
            gemm_tile(xh, wqT, qkv, DIMX, NQKV, nullptr, true, bx, by, sh);
            __threadfence();
            if (t == 0) atomicAdd(&g_cnt1[by], 1);
        } else if (id < AT_END) {
            const int grp = (int)(id - K1_TILES);
            const int rb  = grp >> 2;            // 128-row block
            if (t == 0) {
                while (ld_cg(&g_cnt1[rb]) < 12) { }
            }
            __syncthreads();
            __threadfence();                     // acquire for qkv reads
            attn_group(qkv, att, grp, sh);
            __threadfence();
            if (t == 0) atomicAdd(&g_cnt2[rb], 1);
        } else {
            const int k3 = (int)(id - AT_END);
            const int bx = k3 & 1;
            const int by = k3 >> 1;
            if (t == 0) {
                while (ld_cg(&g_cnt2[by]) < 4) { }
            }
            __syncthreads();
            __threadfence();                     // acquire for att reads
            gemm_tile(att, woT, out, INNER, DIMX, bias, false, bx, by, sh);
        }
        __syncthreads();                         // smem/sid reuse guard
    }
}

// ------------------------- aux kernels --------------------------------------

__global__ void reset_k()
{
    int i = blockIdx.x * blockDim.x + threadIdx.x;
    if (i == 0) g_ticket = 0u;
    if (i < 1024) { g_cnt1[i] = 0; g_cnt2[i] = 0; }
}

__global__ void f2h_kernel(const float* __restrict__ in, __half* __restrict__ out,
                           int n4)
{
    int i = blockIdx.x * blockDim.x + threadIdx.x;
    if (i < n4) {
        float4 v = ((const float4*)in)[i];
        ((uint2*)out)[i] = make_uint2(pack2h(v.x, v.y), pack2h(v.z, v.w));
    }
}

__global__ void transpose_h(const float* __restrict__ in, __half* __restrict__ out,
                            int R, int C)
{
    __shared__ float tile[32][33];
    int c0 = blockIdx.x * 32, r0 = blockIdx.y * 32;
    #pragma unroll
    for (int i = threadIdx.y; i < 32; i += 8)
        tile[i][threadIdx.x] = in[(size_t)(r0 + i) * C + c0 + threadIdx.x];
    __syncthreads();
    #pragma unroll
    for (int i = threadIdx.y; i < 32; i += 8)
        out[(size_t)(c0 + i) * R + r0 + threadIdx.x] =
            __float2half_rn(tile[threadIdx.x][i]);
}

// ------------------------- launch -------------------------------------------

extern "C" void kernel_launch(void* const* d_in, const int* in_sizes, int n_in,
                              void* d_out, int out_size)
{
    const float* x     = (const float*)d_in[0];
    const float* W_qkv = (const float*)d_in[1];
    const float* W_out = (const float*)d_in[2];
    const float* b_out = (const float*)d_in[3];
    float* out = (float*)d_out;

    __half *xh, *qkv, *att, *wqT, *woT;
    cudaGetSymbolAddress((void**)&xh,  g_xh);
    cudaGetSymbolAddress((void**)&qkv, g_qkv);
    cudaGetSymbolAddress((void**)&att, g_attn);
    cudaGetSymbolAddress((void**)&wqT, g_WqkvT);
    cudaGetSymbolAddress((void**)&woT, g_WoutT);

    cudaFuncSetAttribute(mega,
                         cudaFuncAttributeMaxDynamicSharedMemorySize, GSM_BYTES);

    reset_k<<<4, 256>>>();

    const int n4 = TOKENS * DIMX / 4;
    f2h_kernel<<<n4 / 256, 256>>>(x, xh, n4);

    transpose_h<<<dim3(NQKV / 32, DIMX / 32), dim3(32, 8)>>>(W_qkv, wqT, DIMX, NQKV);
    transpose_h<<<dim3(DIMX / 32, INNER / 32), dim3(32, 8)>>>(W_out, woT, INNER, DIMX);

    // persistent mega kernel: K1 + attn + K3 with in-kernel dependencies
    mega<<<NPCTA, 256, GSM_BYTES>>>(xh, wqT, woT, b_out, qkv, att, out);
}

// round 17
// speedup vs baseline: 1.2628x; 1.2628x over previous
#include <cuda_runtime.h>
#include <cuda_fp16.h>
#include <cstdint>

// ---------------------------------------------------------------------------
// Attention_37074157699274 — round 17: dependency-free per-rowblock fusion.
// One kernel, 1024 CTAs; CTA = one 128-row block, fully independent:
//   phase 1: K1 (weight-stationary, r14 body)  -> qkv (gmem, L2-hot)
//   phase 2: attn x4 groups (r11 body)         -> att (gmem, L2-hot)
//   phase 3: K3 x2 col-tiles (r11 body)        -> out (+bias)
// No inter-CTA sync. Aux: x->fp16, weight transposes.
// ---------------------------------------------------------------------------

#define TOKENS   131072
#define GROUPS   4096
#define DIMX     256
#define NQKV     1536
#define INNER    512
#define HEADS    8
#define DH       64
#define ATT_SCALE 0.125f

__device__ __half g_xh  [(size_t)TOKENS * DIMX];
__device__ __half g_qkv [(size_t)TOKENS * NQKV];
__device__ __half g_attn[(size_t)TOKENS * INNER];
__device__ __half g_WqkvT[(size_t)NQKV * DIMX];
__device__ __half g_WoutT[(size_t)DIMX * INNER];

// ------------------------- helpers ------------------------------------------

__device__ __forceinline__ uint32_t pack2h(float x, float y) {
    __half2 h = __halves2half2(__float2half_rn(x), __float2half_rn(y));
    return *reinterpret_cast<uint32_t*>(&h);
}
__device__ __forceinline__ uint32_t smem_u32(const void* p) {
    uint32_t a;
    asm("{ .reg .u64 t; cvta.to.shared.u64 t, %1; cvt.u32.u64 %0, t; }"
        : "=r"(a) : "l"(p));
    return a;
}
__device__ __forceinline__ void cp16(uint32_t saddr, const void* gptr) {
    asm volatile("cp.async.cg.shared.global [%0], [%1], 16;"
                 :: "r"(saddr), "l"(gptr) : "memory");
}
__device__ __forceinline__ void ldsm4(uint32_t r[4], uint32_t addr) {
    asm volatile("ldmatrix.sync.aligned.m8n8.x4.shared.b16 {%0,%1,%2,%3}, [%4];"
                 : "=r"(r[0]), "=r"(r[1]), "=r"(r[2]), "=r"(r[3]) : "r"(addr));
}
__device__ __forceinline__ void ldsm4t(uint32_t r[4], uint32_t addr) {
    asm volatile("ldmatrix.sync.aligned.m8n8.x4.trans.shared.b16 {%0,%1,%2,%3}, [%4];"
                 : "=r"(r[0]), "=r"(r[1]), "=r"(r[2]), "=r"(r[3]) : "r"(addr));
}
__device__ __forceinline__ void mma_f16(float c[4], uint32_t a0, uint32_t a1,
                                        uint32_t a2, uint32_t a3,
                                        uint32_t b0, uint32_t b1) {
    asm volatile(
        "mma.sync.aligned.m16n8k16.row.col.f32.f16.f16.f32 "
        "{%0,%1,%2,%3}, {%4,%5,%6,%7}, {%8,%9}, {%0,%1,%2,%3};\n"
        : "+f"(c[0]), "+f"(c[1]), "+f"(c[2]), "+f"(c[3])
        : "r"(a0), "r"(a1), "r"(a2), "r"(a3), "r"(b0), "r"(b1));
}

// ------------------------- phase 1: K1 rowblock (r14 body) ------------------
// qkv[128,1536] = xh[128,256] @ WqkvT[1536,256]^T for row block `by`.
// A staged once (528-B rows), 12 B col-tiles [128x256] double-buffered.

#define K1STRB  528
#define K1_TILE (128 * K1STRB)            // 67584
#define FSM_BYTES (3 * K1_TILE)           // 202752 (whole-kernel smem)
#define K1_NT   12

__device__ __forceinline__ void k1_rowblock(
    const __half* __restrict__ A, const __half* __restrict__ Bt,
    __half* __restrict__ C, int by, __half* sh)
{
    const uint32_t sb = smem_u32(sh);
    const int t     = threadIdx.x;
    const int lane  = t & 31;
    const int warp  = t >> 5;
    const int warpM = warp & 1;
    const int warpN = warp >> 1;

    const size_t rowBase = (size_t)by * 128;
    const __half* Ag = A + rowBase * DIMX;

    #pragma unroll
    for (int i = 0; i < 16; i++) {
        int g = i * 256 + t, r = g >> 5, s = g & 31;
        cp16(sb + r * K1STRB + s * 16, Ag + (size_t)r * DIMX + s * 8);
    }
    auto stageB = [&](int ct, int buf) {
        const __half* Bg = Bt + (size_t)(ct * 128) * DIMX;
        const uint32_t bD = sb + K1_TILE + buf * K1_TILE;
        #pragma unroll
        for (int i = 0; i < 16; i++) {
            int g = i * 256 + t, r = g >> 5, s = g & 31;
            cp16(bD + r * K1STRB + s * 16, Bg + (size_t)r * DIMX + s * 8);
        }
    };
    stageB(0, 0);
    asm volatile("cp.async.commit_group;" ::: "memory");
    stageB(1, 1);
    asm volatile("cp.async.commit_group;" ::: "memory");

    const int lr    = lane & 15;
    const int aKoff = (lane & 16) ? 16 : 0;
    const int bRow  = (lane & 7) + ((lane & 16) ? 8 : 0);
    const int bKoff = (lane & 8) ? 16 : 0;

    for (int ct = 0; ct < K1_NT; ct++) {
        if (ct < K1_NT - 1) asm volatile("cp.async.wait_group 1;" ::: "memory");
        else                asm volatile("cp.async.wait_group 0;" ::: "memory");
        __syncthreads();

        const uint32_t aB = sb;
        const uint32_t bB = sb + K1_TILE + (ct & 1) * K1_TILE;

        float acc[4][4][4];
        #pragma unroll
        for (int mt = 0; mt < 4; mt++)
            #pragma unroll
            for (int nt = 0; nt < 4; nt++)
                #pragma unroll
                for (int i = 0; i < 4; i++) acc[mt][nt][i] = 0.f;

        #pragma unroll
        for (int ks = 0; ks < 16; ks++) {
            const int k0b = ks * 32;
            uint32_t a[4][4], b[2][4];
            #pragma unroll
            for (int mt = 0; mt < 4; mt++)
                ldsm4(a[mt], aB + (warpM * 64 + mt * 16 + lr) * K1STRB + k0b + aKoff);
            #pragma unroll
            for (int np = 0; np < 2; np++)
                ldsm4(b[np], bB + (warpN * 32 + np * 16 + bRow) * K1STRB + k0b + bKoff);
            #pragma unroll
            for (int nt = 0; nt < 4; nt++) {
                uint32_t b0 = b[nt >> 1][(nt & 1) * 2];
                uint32_t b1 = b[nt >> 1][(nt & 1) * 2 + 1];
                #pragma unroll
                for (int mt = 0; mt < 4; mt++)
                    mma_f16(acc[mt][nt], a[mt][0], a[mt][1], a[mt][2], a[mt][3],
                            b0, b1);
            }
        }
        __syncthreads();

        if (ct + 2 < K1_NT) {
            stageB(ct + 2, ct & 1);
            asm volatile("cp.async.commit_group;" ::: "memory");
        }

        const int colBase = ct * 128;
        #pragma unroll
        for (int mt = 0; mt < 4; mt++) {
            size_t row = rowBase + warpM * 64 + mt * 16 + (lane >> 2);
            #pragma unroll
            for (int nt = 0; nt < 4; nt++) {
                int col = colBase + warpN * 32 + nt * 8 + 2 * (lane & 3);
                *(uint32_t*)(C + row * NQKV + col) =
                    pack2h(acc[mt][nt][0], acc[mt][nt][1]);
                *(uint32_t*)(C + (row + 8) * NQKV + col) =
                    pack2h(acc[mt][nt][2], acc[mt][nt][3]);
            }
        }
    }
}

// ------------------------- phase 2: attn group (r11 body) -------------------

#define ROWH 1544
#define ROWB (ROWH * 2)                   // 3088; 32*ROWB = 98816 <= FSM_BYTES

__device__ __forceinline__ void attn_group(
    const __half* __restrict__ qkv, __half* __restrict__ o, int grp, __half* T)
{
    const uint32_t tb = smem_u32(T);
    const int t    = threadIdx.x;
    const int lane = t & 31;
    const int h    = t >> 5;
    const size_t tokBase = (size_t)grp * 32;

    {
        const __half* src = qkv + tokBase * NQKV;
        #pragma unroll
        for (int i = 0; i < 24; i++) {
            int idx = i * 256 + t;
            int r = idx / 192, c = idx % 192;
            *(uint4*)(T + r * ROWH + c * 8) =
                *(const uint4*)(src + (size_t)r * NQKV + c * 8);
        }
    }
    __syncthreads();

    const uint32_t qOff = tb + h * 128;
    const uint32_t kOff = tb + 1024 + h * 128;
    const uint32_t vOff = tb + 2048 + h * 128;

    const int lr    = lane & 15;
    const int aKoff = (lane & 16) ? 16 : 0;
    const int bRow  = (lane & 7) + ((lane & 16) ? 8 : 0);
    const int bKoff = (lane & 8) ? 16 : 0;
    const int vCoff = (lane & 16) ? 16 : 0;

    float s[2][4][4];
    #pragma unroll
    for (int mt = 0; mt < 2; mt++)
        #pragma unroll
        for (int nt = 0; nt < 4; nt++)
            #pragma unroll
            for (int i = 0; i < 4; i++) s[mt][nt][i] = 0.f;

    #pragma unroll
    for (int kt = 0; kt < 4; kt++) {
        const int k0b = kt * 32;
        uint32_t a[2][4], b[2][4];
        #pragma unroll
        for (int mt = 0; mt < 2; mt++)
            ldsm4(a[mt], qOff + (mt * 16 + lr) * ROWB + k0b + aKoff);
        #pragma unroll
        for (int nb = 0; nb < 2; nb++)
            ldsm4(b[nb], kOff + (nb * 16 + bRow) * ROWB + k0b + bKoff);
        #pragma unroll
        for (int mt = 0; mt < 2; mt++)
            #pragma unroll
            for (int nb = 0; nb < 2; nb++) {
                mma_f16(s[mt][2 * nb    ], a[mt][0], a[mt][1], a[mt][2], a[mt][3],
                        b[nb][0], b[nb][1]);
                mma_f16(s[mt][2 * nb + 1], a[mt][0], a[mt][1], a[mt][2], a[mt][3],
                        b[nb][2], b[nb][3]);
            }
    }

    #pragma unroll
    for (int mt = 0; mt < 2; mt++)
        #pragma unroll
        for (int nt = 0; nt < 4; nt++)
            #pragma unroll
            for (int i = 0; i < 4; i++) s[mt][nt][i] *= ATT_SCALE;

    #pragma unroll
    for (int mt = 0; mt < 2; mt++) {
        float mA = -1e30f, mB = -1e30f;
        #pragma unroll
        for (int nt = 0; nt < 4; nt++) {
            mA = fmaxf(mA, fmaxf(s[mt][nt][0], s[mt][nt][1]));
            mB = fmaxf(mB, fmaxf(s[mt][nt][2], s[mt][nt][3]));
        }
        mA = fmaxf(mA, __shfl_xor_sync(~0u, mA, 1));
        mA = fmaxf(mA, __shfl_xor_sync(~0u, mA, 2));
        mB = fmaxf(mB, __shfl_xor_sync(~0u, mB, 1));
        mB = fmaxf(mB, __shfl_xor_sync(~0u, mB, 2));
        float sA = 0.f, sB = 0.f;
        #pragma unroll
        for (int nt = 0; nt < 4; nt++) {
            s[mt][nt][0] = __expf(s[mt][nt][0] - mA); sA += s[mt][nt][0];
            s[mt][nt][1] = __expf(s[mt][nt][1] - mA); sA += s[mt][nt][1];
            s[mt][nt][2] = __expf(s[mt][nt][2] - mB); sB += s[mt][nt][2];
            s[mt][nt][3] = __expf(s[mt][nt][3] - mB); sB += s[mt][nt][3];
        }
        sA += __shfl_xor_sync(~0u, sA, 1);
        sA += __shfl_xor_sync(~0u, sA, 2);
        sB += __shfl_xor_sync(~0u, sB, 1);
        sB += __shfl_xor_sync(~0u, sB, 2);
        float iA = 1.f / sA, iB = 1.f / sB;
        #pragma unroll
        for (int nt = 0; nt < 4; nt++) {
            s[mt][nt][0] *= iA; s[mt][nt][1] *= iA;
            s[mt][nt][2] *= iB; s[mt][nt][3] *= iB;
        }
    }

    uint32_t pk[2][2][4];
    #pragma unroll
    for (int mt = 0; mt < 2; mt++)
        #pragma unroll
        for (int kt = 0; kt < 2; kt++) {
            pk[mt][kt][0] = pack2h(s[mt][2 * kt    ][0], s[mt][2 * kt    ][1]);
            pk[mt][kt][1] = pack2h(s[mt][2 * kt    ][2], s[mt][2 * kt    ][3]);
            pk[mt][kt][2] = pack2h(s[mt][2 * kt + 1][0], s[mt][2 * kt + 1][1]);
            pk[mt][kt][3] = pack2h(s[mt][2 * kt + 1][2], s[mt][2 * kt + 1][3]);
        }

    float oa[2][8][4];
    #pragma unroll
    for (int mt = 0; mt < 2; mt++)
        #pragma unroll
        for (int nt = 0; nt < 8; nt++)
            #pragma unroll
            for (int i = 0; i < 4; i++) oa[mt][nt][i] = 0.f;

    #pragma unroll
    for (int kt = 0; kt < 2; kt++) {
        #pragma unroll
        for (int hf = 0; hf < 4; hf++) {
            uint32_t b[4];
            ldsm4t(b, vOff + (kt * 16 + lr) * ROWB + hf * 32 + vCoff);
            #pragma unroll
            for (int mt = 0; mt < 2; mt++) {
                mma_f16(oa[mt][2 * hf    ], pk[mt][kt][0], pk[mt][kt][1],
                        pk[mt][kt][2], pk[mt][kt][3], b[0], b[1]);
                mma_f16(oa[mt][2 * hf + 1], pk[mt][kt][0], pk[mt][kt][1],
                        pk[mt][kt][2], pk[mt][kt][3], b[2], b[3]);
            }
        }
    }

    __half* obase = o + tokBase * INNER + h * DH;
    #pragma unroll
    for (int mt = 0; mt < 2; mt++) {
        int row = mt * 16 + (lane >> 2);
        #pragma unroll
        for (int nt = 0; nt < 8; nt++) {
            int col = nt * 8 + 2 * (lane & 3);
            *(uint32_t*)(obase + (size_t)row * INNER + col) =
                pack2h(oa[mt][nt][0], oa[mt][nt][1]);
            *(uint32_t*)(obase + (size_t)(row + 8) * INNER + col) =
                pack2h(oa[mt][nt][2], oa[mt][nt][3]);
        }
    }
}

// ------------------------- phase 3: K3 tile (r11 body) ----------------------
// out[128,128] tile (bx, by) of att[M,512] @ WoutT[256,512]^T + bias.

#define STRB   144
#define A_BYTES (128 * STRB)
#define B_BYTES (128 * STRB)
#define STG_BYTES (A_BYTES + B_BYTES)
#define NSTG   3                           // 110592 <= FSM_BYTES

__device__ __forceinline__ void k3_tile(
    const __half* __restrict__ A, const __half* __restrict__ Bt,
    float* __restrict__ C, const float* __restrict__ bias,
    int bx, int by, __half* sh)
{
    const uint32_t sb = smem_u32(sh);
    const int t     = threadIdx.x;
    const int lane  = t & 31;
    const int warp  = t >> 5;
    const int warpM = warp & 1;
    const int warpN = warp >> 1;

    const size_t rowBase = (size_t)by * 128;
    const int    colBase = bx * 128;
    const int K = INNER, N = DIMX;
    const int NC = K >> 6;

    float acc[4][4][4];
    #pragma unroll
    for (int mt = 0; mt < 4; mt++)
        #pragma unroll
        for (int nt = 0; nt < 4; nt++)
            #pragma unroll
            for (int i = 0; i < 4; i++) acc[mt][nt][i] = 0.f;

    const __half* Ab = A  + rowBase * K;
    const __half* Bb = Bt + (size_t)colBase * K;

    auto stage = [&](int kc) {
        const int slot = kc % NSTG;
        const uint32_t aD = sb + slot * STG_BYTES;
        const uint32_t bD = aD + A_BYTES;
        const __half* As = Ab + kc * 64;
        const __half* Bs = Bb + kc * 64;
        #pragma unroll
        for (int i = 0; i < 4; i++) {
            int g = i * 256 + t, r = g >> 3, s = g & 7;
            cp16(aD + r * STRB + s * 16, As + (size_t)r * K + s * 8);
        }
        #pragma unroll
        for (int i = 0; i < 4; i++) {
            int g = i * 256 + t, r = g >> 3, s = g & 7;
            cp16(bD + r * STRB + s * 16, Bs + (size_t)r * K + s * 8);
        }
        asm volatile("cp.async.commit_group;" ::: "memory");
    };

    stage(0); stage(1);

    const int lr    = lane & 15;
    const int aKoff = (lane & 16) ? 16 : 0;
    const int bRow  = (lane & 7) + ((lane & 16) ? 8 : 0);
    const int bKoff = (lane & 8) ? 16 : 0;

    for (int kc = 0; kc < NC; kc++) {
        if (kc < NC - 1) asm volatile("cp.async.wait_group 1;" ::: "memory");
        else             asm volatile("cp.async.wait_group 0;" ::: "memory");
        __syncthreads();
        if (kc + 2 < NC) stage(kc + 2);

        const uint32_t aB = sb + (kc % NSTG) * STG_BYTES;
        const uint32_t bB = aB + A_BYTES;

        #pragma unroll
        for (int ks = 0; ks < 4; ks++) {
            const int k0b = ks * 32;
            uint32_t a[4][4], b[2][4];
            #pragma unroll
            for (int mt = 0; mt < 4; mt++)
                ldsm4(a[mt], aB + (warpM * 64 + mt * 16 + lr) * STRB + k0b + aKoff);
            #pragma unroll
            for (int np = 0; np < 2; np++)
                ldsm4(b[np], bB + (warpN * 32 + np * 16 + bRow) * STRB + k0b + bKoff);
            #pragma unroll
            for (int nt = 0; nt < 4; nt++) {
                uint32_t b0 = b[nt >> 1][(nt & 1) * 2];
                uint32_t b1 = b[nt >> 1][(nt & 1) * 2 + 1];
                #pragma unroll
                for (int mt = 0; mt < 4; mt++)
                    mma_f16(acc[mt][nt], a[mt][0], a[mt][1], a[mt][2], a[mt][3],
                            b0, b1);
            }
        }
    }

    #pragma unroll
    for (int mt = 0; mt < 4; mt++) {
        size_t row = rowBase + warpM * 64 + mt * 16 + (lane >> 2);
        #pragma unroll
        for (int nt = 0; nt < 4; nt++) {
            int col = colBase + warpN * 32 + nt * 8 + 2 * (lane & 3);
            float b0 = bias[col], b1 = bias[col + 1];
            *(float2*)(C + row * N + col) =
                make_float2(acc[mt][nt][0] + b0, acc[mt][nt][1] + b1);
            *(float2*)(C + (row + 8) * N + col) =
                make_float2(acc[mt][nt][2] + b0, acc[mt][nt][3] + b1);
        }
    }
}

// ------------------------- fused kernel -------------------------------------

__global__ __launch_bounds__(256, 1)
void fused(const __half* __restrict__ xh, const __half* __restrict__ wqT,
           const __half* __restrict__ woT, const float* __restrict__ bias,
           __half* __restrict__ qkv, __half* __restrict__ att,
           float* __restrict__ out)
{
    extern __shared__ __half sh[];
    const int by = blockIdx.x;

    // phase 1: qkv rows [128*by, +128)
    k1_rowblock(xh, wqT, qkv, by, sh);
    __syncthreads();

    // phase 2: 4 attention groups of this row block (L2-hot qkv)
    #pragma unroll 1
    for (int g = 0; g < 4; g++) {
        attn_group(qkv, att, by * 4 + g, sh);
        __syncthreads();
    }

    // phase 3: out rows [128*by, +128), 2 col tiles (L2-hot att)
    #pragma unroll 1
    for (int bx = 0; bx < 2; bx++) {
        k3_tile(att, woT, out, bias, bx, by, sh);
        __syncthreads();
    }
}

// ------------------------- aux kernels --------------------------------------

__global__ void f2h_kernel(const float* __restrict__ in, __half* __restrict__ out,
                           int n4)
{
    int i = blockIdx.x * blockDim.x + threadIdx.x;
    if (i < n4) {
        float4 v = ((const float4*)in)[i];
        ((uint2*)out)[i] = make_uint2(pack2h(v.x, v.y), pack2h(v.z, v.w));
    }
}

__global__ void transpose_h(const float* __restrict__ in, __half* __restrict__ out,
                            int R, int C)
{
    __shared__ float tile[32][33];
    int c0 = blockIdx.x * 32, r0 = blockIdx.y * 32;
    #pragma unroll
    for (int i = threadIdx.y; i < 32; i += 8)
        tile[i][threadIdx.x] = in[(size_t)(r0 + i) * C + c0 + threadIdx.x];
    __syncthreads();
    #pragma unroll
    for (int i = threadIdx.y; i < 32; i += 8)
        out[(size_t)(c0 + i) * R + r0 + threadIdx.x] =
            __float2half_rn(tile[threadIdx.x][i]);
}

// ------------------------- launch -------------------------------------------

extern "C" void kernel_launch(void* const* d_in, const int* in_sizes, int n_in,
                              void* d_out, int out_size)
{
    const float* x     = (const float*)d_in[0];
    const float* W_qkv = (const float*)d_in[1];
    const float* W_out = (const float*)d_in[2];
    const float* b_out = (const float*)d_in[3];
    float* out = (float*)d_out;

    __half *xh, *qkv, *att, *wqT, *woT;
    cudaGetSymbolAddress((void**)&xh,  g_xh);
    cudaGetSymbolAddress((void**)&qkv, g_qkv);
    cudaGetSymbolAddress((void**)&att, g_attn);
    cudaGetSymbolAddress((void**)&wqT, g_WqkvT);
    cudaGetSymbolAddress((void**)&woT, g_WoutT);

    cudaFuncSetAttribute(fused,
                         cudaFuncAttributeMaxDynamicSharedMemorySize, FSM_BYTES);

    const int n4 = TOKENS * DIMX / 4;
    f2h_kernel<<<n4 / 256, 256>>>(x, xh, n4);

    transpose_h<<<dim3(NQKV / 32, DIMX / 32), dim3(32, 8)>>>(W_qkv, wqT, DIMX, NQKV);
    transpose_h<<<dim3(DIMX / 32, INNER / 32), dim3(32, 8)>>>(W_out, woT, INNER, DIMX);

    // fused K1 + attn + K3, one CTA per 128-row block
    fused<<<TOKENS / 128, 256, FSM_BYTES>>>(xh, wqT, woT, b_out, qkv, att, out);
}